// round 15
// baseline (speedup 1.0000x reference)
#include <cuda_runtime.h>
#include <cuda_bf16.h>
#include <cstdint>

#define NTHR 256
using ushort_t = unsigned short;

constexpr int B_  = 2;
constexpr int N_  = 256;
constexpr int DC_ = 96;
constexpr int DP_ = 160;
constexpr int DE_ = 64;
constexpr int H_  = 8;
constexpr int KT  = 32;        // k rows per tile
constexpr int NT_ = 8;         // tiles
constexpr int LDE = 72;        // bf16 elems
constexpr int LDX = 264;
constexpr int LDY = 168;
constexpr int LDWS = 40;       // staged weight row stride (ushorts)
constexpr int WSB  = 12800;    // one weight buffer (bytes) = 160 rows * 80 B

// ---------------- device scratch (fp32) ----------------
__device__ float g_Qcat[B_*N_*256];   // [Qc*inv_sqrt96 | Qp*inv_sqrt160]
__device__ float g_Kcat[B_*N_*256];   // [Kc | Kp]
__device__ float g_Vc[B_*N_*DC_];
__device__ float g_Vp[B_*N_*DP_];

// ---------------- split-bf16 weights, contiguous K16 chunks ----------------
// addr: (k>>4)*(N*32) + n*32 + (k&15)  (hi), +16 (lo). Chunk = N*32 ush contiguous.
__device__ __align__(16) ushort_t gW1mulC[4*96*32];   // K=64,  N=96
__device__ __align__(16) ushort_t gW1mulP[4*160*32];  // K=64,  N=160
__device__ __align__(16) ushort_t gW1addC[4*96*32];
__device__ __align__(16) ushort_t gW1addP[4*160*32];
__device__ __align__(16) ushort_t gWc1[6*96*32];      // K=96,  N=96
__device__ __align__(16) ushort_t gWc2[6*96*32];
__device__ __align__(16) ushort_t gWp1[10*160*32];    // K=160, N=160
__device__ __align__(16) ushort_t gWp2[10*160*32];
__device__ __align__(16) ushort_t gWe[16*64*32];      // K=256 (permuted), N=64

// ---------------- shared memory byte offsets (per-CTA total 103680 B) -------
constexpr int OFFB_Q   = 0;        // 256 f
constexpr int OFFB_WV  = 1024;     // 256 f
constexpr int OFFB_SCC = 2048;     // 2048 f
constexpr int OFFB_SCP = 10240;    // 2048 f
constexpr int OFFB_MB  = 18432;    // 256 f
constexpr int OFFB_AB  = 19456;    // 256 f
constexpr int OFFB_CB1 = 20480;    // 96 f
constexpr int OFFB_CB2 = 20864;
constexpr int OFFB_PB1 = 21248;    // 160 f
constexpr int OFFB_PB2 = 21888;
constexpr int OFFB_BE  = 22528;    // 64 f
// E/Y union (21504 B): E used in stage-1 only; Y (MLP hidden) reuses it after.
constexpr int OFFB_EHI = 22784;    // 32*72*2  = 4608 B
constexpr int OFFB_ELO = 27392;
constexpr int OFFB_YHI = 22784;    // 32*168*2 = 10752 B
constexpr int OFFB_YLO = 33536;
constexpr int OFFB_XHI = 44288;    // 32*264*2 = 16896 B
constexpr int OFFB_XLO = 61184;
constexpr int OFFB_WS  = 78080;    // 2 * 12800 B ping-pong weight buffers
constexpr int SMEM_BYTES = 103680;

// ---------------- helpers ----------------
__device__ __forceinline__ float bf2f(ushort_t u) {
    return __uint_as_float(((unsigned)u) << 16);
}
__device__ __forceinline__ void split2(float x0, float x1, unsigned& hi, unsigned& lo) {
    const ushort_t h0 = __bfloat16_as_ushort(__float2bfloat16_rn(x0));
    const ushort_t h1 = __bfloat16_as_ushort(__float2bfloat16_rn(x1));
    const ushort_t l0 = __bfloat16_as_ushort(__float2bfloat16_rn(x0 - bf2f(h0)));
    const ushort_t l1 = __bfloat16_as_ushort(__float2bfloat16_rn(x1 - bf2f(h1)));
    hi = (unsigned)h0 | ((unsigned)h1 << 16);
    lo = (unsigned)l0 | ((unsigned)l1 << 16);
}
__device__ __forceinline__ void mma_bf16(float (&d)[4], const unsigned (&a)[4],
                                         const unsigned (&b)[2]) {
    asm("mma.sync.aligned.m16n8k16.row.col.f32.bf16.bf16.f32 "
        "{%0,%1,%2,%3},{%4,%5,%6,%7},{%8,%9},{%0,%1,%2,%3};"
        : "+f"(d[0]), "+f"(d[1]), "+f"(d[2]), "+f"(d[3])
        : "r"(a[0]), "r"(a[1]), "r"(a[2]), "r"(a[3]), "r"(b[0]), "r"(b[1]));
}
__device__ __forceinline__ float lrelu(float v) { return v > 0.f ? v : 0.05f * v; }

__device__ __forceinline__ uint32_t smem_u32(const void* p) {
    uint32_t a;
    asm("{ .reg .u64 t; cvta.to.shared.u64 t, %1; cvt.u32.u64 %0, t; }"
        : "=r"(a) : "l"(p));
    return a;
}
__device__ __forceinline__ void cpa16(uint32_t dst, const void* src) {
    asm volatile("cp.async.cg.shared.global [%0], [%1], 16;"
                 :: "r"(dst), "l"(src) : "memory");
}
#define CPA_COMMIT  asm volatile("cp.async.commit_group;" ::: "memory")
#define CPA_WAIT1   asm volatile("cp.async.wait_group 1;" ::: "memory")
#define CPA_WAIT0   asm volatile("cp.async.wait_group 0;" ::: "memory")

// global weight address (hi element; lo at +16)
__device__ __forceinline__ int waddr(int k, int n, int N) {
    return (k >> 4) * (N * 32) + n * 32 + (k & 15);
}

// ============================= prep: QKV =============================
__global__ void __launch_bounds__(NTHR) prep_kernel(
    const float* __restrict__ classes, const float* __restrict__ params,
    const float* __restrict__ wc_qkv,  const float* __restrict__ bc_qkv,
    const float* __restrict__ wp_qkv,  const float* __restrict__ bp_qkv)
{
    __shared__ float rc[DC_];
    __shared__ float rp[DP_];
    const int bn = blockIdx.x;
    const int t  = threadIdx.x;
    if (t < DC_) rc[t] = classes[bn*DC_ + t];
    if (t < DP_) rp[t] = params[bn*DP_ + t];
    __syncthreads();

    const float invc = 0.10206207261596575f;   // 1/sqrt(96)
    const float invp = 0.07905694150420949f;   // 1/sqrt(160)

    for (int o = t; o < 3*DC_; o += NTHR) {
        float acc = bc_qkv[o];
        #pragma unroll 4
        for (int i = 0; i < DC_; i++) acc = fmaf(rc[i], wc_qkv[i*3*DC_ + o], acc);
        const int part = o / DC_, d = o - part*DC_;
        if (part == 0)      g_Qcat[bn*256 + d] = acc * invc;
        else if (part == 1) g_Kcat[bn*256 + d] = acc;
        else                g_Vc[bn*DC_ + d] = acc;
    }
    for (int o = t; o < 3*DP_; o += NTHR) {
        float acc = bp_qkv[o];
        #pragma unroll 4
        for (int i = 0; i < DP_; i++) acc = fmaf(rp[i], wp_qkv[i*3*DP_ + o], acc);
        const int part = o / DP_, d = o - part*DP_;
        if (part == 0)      g_Qcat[bn*256 + 96 + d] = acc * invp;
        else if (part == 1) g_Kcat[bn*256 + 96 + d] = acc;
        else                g_Vp[bn*DP_ + d] = acc;
    }
}

// ============================= prep: weight split/pack =============================
__global__ void __launch_bounds__(NTHR) pack_kernel(
    const float* __restrict__ fc_mul_w, const float* __restrict__ fc_add_w,
    const float* __restrict__ fc_m1_w,  const float* __restrict__ fc_m2_w,
    const float* __restrict__ fp_mul_w, const float* __restrict__ fp_add_w,
    const float* __restrict__ fp_m1_w,  const float* __restrict__ fp_m2_w,
    const float* __restrict__ we_out)
{
    int i = blockIdx.x * NTHR + threadIdx.x;
    float v; ushort_t* dst; int addr;
    if (i < 32768) {                                   // W1 mul/add, K=64 N=256
        const bool isAdd = i >= 16384;
        const int t = i & 16383, k = t >> 8, n = t & 255;
        if (n < 96) {
            v = (isAdd ? fc_add_w : fc_mul_w)[k*96 + n];
            dst = isAdd ? gW1addC : gW1mulC; addr = waddr(k, n, 96);
        } else {
            v = (isAdd ? fp_add_w : fp_mul_w)[k*160 + n - 96];
            dst = isAdd ? gW1addP : gW1mulP; addr = waddr(k, n - 96, 160);
        }
    } else if ((i -= 32768) < 18432) {                 // Wc m1/m2, K=96 N=96
        const bool l2 = i >= 9216;
        const int t = l2 ? i - 9216 : i, k = t / 96, n = t % 96;
        v = (l2 ? fc_m2_w : fc_m1_w)[k*96 + n];
        dst = l2 ? gWc2 : gWc1; addr = waddr(k, n, 96);
    } else if ((i -= 18432) < 51200) {                 // Wp m1/m2, K=160 N=160
        const bool l2 = i >= 25600;
        const int t = l2 ? i - 25600 : i, k = t / 160, n = t % 160;
        v = (l2 ? fp_m2_w : fp_m1_w)[k*160 + n];
        dst = l2 ? gWp2 : gWp1; addr = waddr(k, n, 160);
    } else if ((i -= 51200) < 16384) {                 // We, K=256 (permuted) N=64
        const int k = i >> 6, n = i & 63;
        const int src = k < 96 ? (k/12)*32 + (k%12)
                               : ((k-96)/20)*32 + 12 + ((k-96)%20);
        v = we_out[src*64 + n];
        dst = gWe; addr = waddr(k, n, 64);
    } else return;
    const ushort_t h = __bfloat16_as_ushort(__float2bfloat16_rn(v));
    const ushort_t l = __bfloat16_as_ushort(__float2bfloat16_rn(v - bf2f(h)));
    dst[addr]      = h;
    dst[addr + 16] = l;
}

// ---------------- A fragment load (row-major bf16, m16 tile) ----------------
__device__ __forceinline__ void ldA(unsigned (&A)[4], const ushort_t* base,
                                    int lda, int row, int col) {
    const ushort_t* p = base + row*lda + col;
    A[0] = *reinterpret_cast<const unsigned*>(p);
    A[1] = *reinterpret_cast<const unsigned*>(p + 8*lda);
    A[2] = *reinterpret_cast<const unsigned*>(p + 8);
    A[3] = *reinterpret_cast<const unsigned*>(p + 8*lda + 8);
}

// ---------------- one K=16 chunk, 3-product split mma ----------------
template<int NTILES>
__device__ __forceinline__ void mma_chunk16(
    const ushort_t* __restrict__ Ahi, const ushort_t* __restrict__ Alo,
    int lda, int acol,
    const ushort_t* __restrict__ W, int nb,
    float (&acc)[NTILES][4], int lane, int mg)
{
    const int g = lane >> 2, t = lane & 3;
    unsigned Ah[4], Al[4];
    const int row = mg*16 + g;
    const int col = acol + 2*t;
    ldA(Ah, Ahi, lda, row, col);
    ldA(Al, Alo, lda, row, col);
    #pragma unroll
    for (int nt = 0; nt < NTILES; nt++) {
        const ushort_t* wp = W + (nb + nt*8 + g)*LDWS + 2*t;
        unsigned Bh[2], Bl[2];
        Bh[0] = *reinterpret_cast<const unsigned*>(wp);
        Bh[1] = *reinterpret_cast<const unsigned*>(wp + 8);
        Bl[0] = *reinterpret_cast<const unsigned*>(wp + 16);
        Bl[1] = *reinterpret_cast<const unsigned*>(wp + 24);
        mma_bf16(acc[nt], Ah, Bh);
        mma_bf16(acc[nt], Ah, Bl);
        mma_bf16(acc[nt], Al, Bh);
    }
}

// ---------------- cp.async chunk prefetch (K16 chunk = Nrows * 64 B) --------
__device__ __forceinline__ void prefetch_chunk(const ushort_t* __restrict__ gW,
                                               int ch, int Nrows,
                                               uint32_t dstaddr, int tid)
{
    const ushort_t* src = gW + ch * Nrows * 32;
    for (int u = tid; u < Nrows * 4; u += NTHR) {
        const int n = u >> 2, q = u & 3;
        cpa16(dstaddr + n*80 + q*16, src + n*32 + q*8);
    }
    CPA_COMMIT;
}

// ---------------- double-buffered pipelined GEMM driver ----------------
template<int NTILES, int NCH>
__device__ __forceinline__ void gemm_run(
    const ushort_t* __restrict__ gW, int Nrows,
    const ushort_t* __restrict__ Ahi, const ushort_t* __restrict__ Alo,
    int lda, int abase,
    ushort_t* sWS, uint32_t wsaddr, int nb, float (&acc)[NTILES][4],
    int tid, int lane, int mg)
{
    prefetch_chunk(gW, 0, Nrows, wsaddr, tid);
    #pragma unroll 1
    for (int ch = 0; ch < NCH; ch++) {
        if (ch + 1 < NCH) {
            prefetch_chunk(gW, ch + 1, Nrows, wsaddr + ((ch + 1) & 1) * WSB, tid);
            CPA_WAIT1;
        } else {
            CPA_WAIT0;
        }
        __syncthreads();
        mma_chunk16<NTILES>(Ahi, Alo, lda, abase + ch*16,
                            sWS + (ch & 1) * (WSB/2), nb, acc, lane, mg);
        __syncthreads();
    }
}

// ---------------- MLP epilogue: lrelu(acc + bias) -> split store ----------------
template<int NTILES>
__device__ __forceinline__ void mlp_epi(
    float (&acc)[NTILES][4], const float* __restrict__ bias, int nbase,
    ushort_t* __restrict__ Dhi, ushort_t* __restrict__ Dlo, int ldd, int coff,
    int lane, int mg)
{
    const int g = lane >> 2, t = lane & 3;
    const int rb = mg*16 + g;
    #pragma unroll
    for (int nt = 0; nt < NTILES; nt++) {
        const int c = nbase + nt*8 + 2*t;
        const float b0 = bias[c], b1 = bias[c+1];
        unsigned h, l;
        split2(lrelu(acc[nt][0] + b0), lrelu(acc[nt][1] + b1), h, l);
        *reinterpret_cast<unsigned*>(&Dhi[rb*ldd + coff + c]) = h;
        *reinterpret_cast<unsigned*>(&Dlo[rb*ldd + coff + c]) = l;
        split2(lrelu(acc[nt][2] + b0), lrelu(acc[nt][3] + b1), h, l);
        *reinterpret_cast<unsigned*>(&Dhi[(rb+8)*ldd + coff + c]) = h;
        *reinterpret_cast<unsigned*>(&Dlo[(rb+8)*ldd + coff + c]) = l;
    }
}

// ============================= fused main kernel =============================
__global__ void __launch_bounds__(NTHR, 2) fused_kernel(
    const float* __restrict__ edges,
    const float* __restrict__ fc_mul_b, const float* __restrict__ fc_add_b,
    const float* __restrict__ fc_m1_b,  const float* __restrict__ fc_m2_b,
    const float* __restrict__ fp_mul_b, const float* __restrict__ fp_add_b,
    const float* __restrict__ fp_m1_b,  const float* __restrict__ fp_m2_b,
    const float* __restrict__ wc_out,   const float* __restrict__ bc_out,
    const float* __restrict__ wp_out,   const float* __restrict__ bp_out,
    const float* __restrict__ be_out,
    float* __restrict__ out)
{
    extern __shared__ char smc[];
    float* sQ   = reinterpret_cast<float*>(smc + OFFB_Q);
    float* sWV  = reinterpret_cast<float*>(smc + OFFB_WV);
    float* sScC = reinterpret_cast<float*>(smc + OFFB_SCC);
    float* sScP = reinterpret_cast<float*>(smc + OFFB_SCP);
    float* sMB  = reinterpret_cast<float*>(smc + OFFB_MB);
    float* sAB  = reinterpret_cast<float*>(smc + OFFB_AB);
    float* sCB1 = reinterpret_cast<float*>(smc + OFFB_CB1);
    float* sCB2 = reinterpret_cast<float*>(smc + OFFB_CB2);
    float* sPB1 = reinterpret_cast<float*>(smc + OFFB_PB1);
    float* sPB2 = reinterpret_cast<float*>(smc + OFFB_PB2);
    float* sBE  = reinterpret_cast<float*>(smc + OFFB_BE);
    ushort_t* sEhi = reinterpret_cast<ushort_t*>(smc + OFFB_EHI);
    ushort_t* sElo = reinterpret_cast<ushort_t*>(smc + OFFB_ELO);
    ushort_t* sYhi = reinterpret_cast<ushort_t*>(smc + OFFB_YHI);
    ushort_t* sYlo = reinterpret_cast<ushort_t*>(smc + OFFB_YLO);
    ushort_t* sXhi = reinterpret_cast<ushort_t*>(smc + OFFB_XHI);
    ushort_t* sXlo = reinterpret_cast<ushort_t*>(smc + OFFB_XLO);
    ushort_t* sWS  = reinterpret_cast<ushort_t*>(smc + OFFB_WS);
    const uint32_t wsaddr = smem_u32(smc + OFFB_WS);

    const int tid  = threadIdx.x;
    const int warp = tid >> 5;
    const int lane = tid & 31;
    const int mg   = warp >> 2;      // 0..1 row group (16 rows)
    const int ng   = warp & 3;       // 0..3 col group
    const int g    = lane >> 2, t4 = lane & 3;
    const int bq   = blockIdx.x;
    const int b    = bq >> 8;

    // persistent stages
    for (int i = tid; i < 256; i += NTHR) sQ[i] = g_Qcat[bq*256 + i];
    for (int i = tid; i < DC_; i += NTHR) {
        sMB[i]  = fc_mul_b[i];  sAB[i]  = fc_add_b[i];
        sCB1[i] = fc_m1_b[i];   sCB2[i] = fc_m2_b[i];
    }
    for (int i = tid; i < DP_; i += NTHR) {
        sMB[96+i] = fp_mul_b[i];  sAB[96+i] = fp_add_b[i];
        sPB1[i]   = fp_m1_b[i];   sPB2[i]   = fp_m2_b[i];
    }
    if (tid < DE_) sBE[tid] = be_out[tid];

    const float* Eb = edges + (size_t)bq * N_ * DE_;
    float* outE = out + (size_t)(B_*N_*DC_ + B_*N_*DP_) + (size_t)bq * N_ * DE_;

    for (int tt = 0; tt < NT_; tt++) {
        const int k0 = tt * KT;
        __syncthreads();
        // ---- load + split E tile ----
        for (int idx = tid; idx < KT*32; idx += NTHR) {
            const int r = idx >> 5, kp = (idx & 31) * 2;
            const float2 e2 = *reinterpret_cast<const float2*>(
                &Eb[(size_t)(k0 + r)*DE_ + kp]);
            unsigned h, l; split2(e2.x, e2.y, h, l);
            *reinterpret_cast<unsigned*>(&sEhi[r*LDE + kp]) = h;
            *reinterpret_cast<unsigned*>(&sElo[r*LDE + kp]) = l;
        }
        // ========== stage 1 pass A: m = E @ Wmul + mb  (class then param) ====
        {
            float acc[3][4] = {};
            gemm_run<3,4>(gW1mulC, 96, sEhi, sElo, LDE, 0, sWS, wsaddr, ng*24,
                          acc, tid, lane, mg);
            const int rb = mg*16 + g;
            #pragma unroll
            for (int nt = 0; nt < 3; nt++) {
                const int c = ng*24 + nt*8 + 2*t4;
                const float mb0 = sMB[c], mb1 = sMB[c+1];
                #pragma unroll
                for (int hh = 0; hh < 2; hh++) {
                    const int r = rb + hh*8;
                    unsigned h, l;
                    split2(acc[nt][2*hh+0] + mb0, acc[nt][2*hh+1] + mb1, h, l);
                    *reinterpret_cast<unsigned*>(&sXhi[r*LDX + c]) = h;
                    *reinterpret_cast<unsigned*>(&sXlo[r*LDX + c]) = l;
                }
            }
        }
        {
            float acc[5][4] = {};
            gemm_run<5,4>(gW1mulP, 160, sEhi, sElo, LDE, 0, sWS, wsaddr, ng*40,
                          acc, tid, lane, mg);
            const int rb = mg*16 + g;
            #pragma unroll
            for (int nt = 0; nt < 5; nt++) {
                const int cp = ng*40 + nt*8 + 2*t4;
                const float mb0 = sMB[96+cp], mb1 = sMB[96+cp+1];
                #pragma unroll
                for (int hh = 0; hh < 2; hh++) {
                    const int r = rb + hh*8;
                    unsigned h, l;
                    split2(acc[nt][2*hh+0] + mb0, acc[nt][2*hh+1] + mb1, h, l);
                    *reinterpret_cast<unsigned*>(&sXhi[r*LDX + 96 + cp]) = h;
                    *reinterpret_cast<unsigned*>(&sXlo[r*LDX + 96 + cp]) = l;
                }
            }
        }
        // ========== stage 1 pass B: add-GEMM + FiLM epilogue ==================
        {
            float acc[3][4] = {};
            gemm_run<3,4>(gW1addC, 96, sEhi, sElo, LDE, 0, sWS, wsaddr, ng*24,
                          acc, tid, lane, mg);
            const int rb = mg*16 + g;
            #pragma unroll
            for (int nt = 0; nt < 3; nt++) {
                const int c = ng*24 + nt*8 + 2*t4;
                const float q0 = sQ[c], q1 = sQ[c+1];
                const float ab0 = sAB[c], ab1 = sAB[c+1];
                #pragma unroll
                for (int hh = 0; hh < 2; hh++) {
                    const int r = rb + hh*8;
                    const float m0 = bf2f(sXhi[r*LDX + c]) + bf2f(sXlo[r*LDX + c]);
                    const float m1 = bf2f(sXhi[r*LDX + c + 1]) + bf2f(sXlo[r*LDX + c + 1]);
                    const float2 kv = *reinterpret_cast<const float2*>(
                        &g_Kcat[(size_t)(b*N_ + k0 + r)*256 + c]);
                    const float a0 = q0 * kv.x, a1 = q1 * kv.y;
                    const float x0 = fmaf(a0, m0, acc[nt][2*hh+0] + ab0 + a0);
                    const float x1 = fmaf(a1, m1, acc[nt][2*hh+1] + ab1 + a1);
                    unsigned h, l; split2(x0, x1, h, l);
                    *reinterpret_cast<unsigned*>(&sXhi[r*LDX + c]) = h;
                    *reinterpret_cast<unsigned*>(&sXlo[r*LDX + c]) = l;
                }
            }
        }
        {
            float acc[5][4] = {};
            gemm_run<5,4>(gW1addP, 160, sEhi, sElo, LDE, 0, sWS, wsaddr, ng*40,
                          acc, tid, lane, mg);
            const int rb = mg*16 + g;
            #pragma unroll
            for (int nt = 0; nt < 5; nt++) {
                const int cp = ng*40 + nt*8 + 2*t4;
                const int c = 96 + cp;
                const float q0 = sQ[c], q1 = sQ[c+1];
                const float ab0 = sAB[c], ab1 = sAB[c+1];
                #pragma unroll
                for (int hh = 0; hh < 2; hh++) {
                    const int r = rb + hh*8;
                    const float m0 = bf2f(sXhi[r*LDX + c]) + bf2f(sXlo[r*LDX + c]);
                    const float m1 = bf2f(sXhi[r*LDX + c + 1]) + bf2f(sXlo[r*LDX + c + 1]);
                    const float2 kv = *reinterpret_cast<const float2*>(
                        &g_Kcat[(size_t)(b*N_ + k0 + r)*256 + c]);
                    const float a0 = q0 * kv.x, a1 = q1 * kv.y;
                    const float x0 = fmaf(a0, m0, acc[nt][2*hh+0] + ab0 + a0);
                    const float x1 = fmaf(a1, m1, acc[nt][2*hh+1] + ab1 + a1);
                    unsigned h, l; split2(x0, x1, h, l);
                    *reinterpret_cast<unsigned*>(&sXhi[r*LDX + c]) = h;
                    *reinterpret_cast<unsigned*>(&sXlo[r*LDX + c]) = l;
                }
            }
        }
        __syncthreads();   // E consumed; Y (aliased) may now be written
        // ================= class MLP layer 1 (X[0:96] -> Y[0:96]) ============
        {
            float acc[3][4] = {};
            gemm_run<3,6>(gWc1, 96, sXhi, sXlo, LDX, 0, sWS, wsaddr, ng*24,
                          acc, tid, lane, mg);
            mlp_epi<3>(acc, sCB1, ng*24, sYhi, sYlo, LDY, 0, lane, mg);
        }
        __syncthreads();
        // ================= class MLP layer 2 (Y[0:96] -> X[0:96]) ============
        {
            float acc[3][4] = {};
            gemm_run<3,6>(gWc2, 96, sYhi, sYlo, LDY, 0, sWS, wsaddr, ng*24,
                          acc, tid, lane, mg);
            mlp_epi<3>(acc, sCB2, ng*24, sXhi, sXlo, LDX, 0, lane, mg);
        }
        __syncthreads();
        // ================= param MLP layer 1 (X[96:256] -> Y[0:160]) =========
        {
            float acc[5][4] = {};
            gemm_run<5,10>(gWp1, 160, sXhi, sXlo, LDX, 96, sWS, wsaddr, ng*40,
                           acc, tid, lane, mg);
            mlp_epi<5>(acc, sPB1, ng*40, sYhi, sYlo, LDY, 0, lane, mg);
        }
        __syncthreads();
        // ================= param MLP layer 2 (Y[0:160] -> X[96:256]) =========
        {
            float acc[5][4] = {};
            gemm_run<5,10>(gWp2, 160, sYhi, sYlo, LDY, 0, sWS, wsaddr, ng*40,
                           acc, tid, lane, mg);
            mlp_epi<5>(acc, sPB2, ng*40, sXhi, sXlo, LDX, 96, lane, mg);
        }
        __syncthreads();
        // ---- per-head score sums from y2 (hi+lo reconstruction) ----
        for (int tau = tid; tau < KT*16; tau += NTHR) {
            const int r = tau >> 4;
            const int rest = tau & 15;
            const int h = rest >> 1;
            float s = 0.f;
            if ((rest & 1) == 0) {
                const int base = r*LDX + h*12;
                #pragma unroll
                for (int d = 0; d < 12; d++)
                    s += bf2f(sXhi[base+d]) + bf2f(sXlo[base+d]);
                sScC[(k0 + r)*H_ + h] = s;
            } else {
                const int base = r*LDX + 96 + h*20;
                #pragma unroll
                for (int d = 0; d < 20; d++)
                    s += bf2f(sXhi[base+d]) + bf2f(sXlo[base+d]);
                sScP[(k0 + r)*H_ + h] = s;
            }
        }
        // ================= out_e GEMM (X[0:256] -> 64) =======================
        {
            float acc[2][4] = {};
            gemm_run<2,16>(gWe, 64, sXhi, sXlo, LDX, 0, sWS, wsaddr, ng*16,
                           acc, tid, lane, mg);
            const int rb = mg*16 + g;
            #pragma unroll
            for (int nt = 0; nt < 2; nt++) {
                const int c = ng*16 + nt*8 + 2*t4;
                const float b0 = sBE[c], b1 = sBE[c+1];
                float2 v0, v1;
                v0.x = acc[nt][0] + b0; v0.y = acc[nt][1] + b1;
                v1.x = acc[nt][2] + b0; v1.y = acc[nt][3] + b1;
                *reinterpret_cast<float2*>(&outE[(size_t)(k0 + rb)*DE_ + c]) = v0;
                *reinterpret_cast<float2*>(&outE[(size_t)(k0 + rb + 8)*DE_ + c]) = v1;
            }
        }
    }
    __syncthreads();

    // ---- softmax over k per head (warp h owns head h) ----
    {
        const int h = warp;
        #pragma unroll
        for (int ty = 0; ty < 2; ty++) {
            float* S = ty ? sScP : sScC;
            float m = -1e30f;
            for (int k = lane; k < N_; k += 32) m = fmaxf(m, S[k*H_ + h]);
            #pragma unroll
            for (int o = 16; o; o >>= 1) m = fmaxf(m, __shfl_xor_sync(0xffffffffu, m, o));
            float sum = 0.f;
            for (int k = lane; k < N_; k += 32) {
                const float e = __expf(S[k*H_ + h] - m);
                S[k*H_ + h] = e;
                sum += e;
            }
            #pragma unroll
            for (int o = 16; o; o >>= 1) sum += __shfl_xor_sync(0xffffffffu, sum, o);
            const float inv = 1.f / sum;
            for (int k = lane; k < N_; k += 32) S[k*H_ + h] *= inv;
        }
    }
    __syncthreads();

    // ---- weighted V (cross: ap weights Vc, ac weights Vp) ----
    {
        float acc = 0.f;
        if (tid < DC_) {
            const int c = tid, h = c / 12;
            const float* V = g_Vc + (size_t)(b*N_) * DC_ + c;
            for (int k = 0; k < N_; k++) acc = fmaf(sScP[k*H_ + h], V[(size_t)k*DC_], acc);
        } else {
            const int p = tid - DC_, h = p / 20;
            const float* V = g_Vp + (size_t)(b*N_) * DP_ + p;
            for (int k = 0; k < N_; k++) acc = fmaf(sScC[k*H_ + h], V[(size_t)k*DP_], acc);
        }
        sWV[tid] = acc;
    }
    __syncthreads();

    // ---- output projections ----
    if (tid < DC_) {
        const int o = tid;
        float acc = bc_out[o];
        for (int c = 0; c < DC_; c++) acc = fmaf(sWV[c], wc_out[c*DC_ + o], acc);
        out[(size_t)bq*DC_ + o] = acc;
    } else {
        const int o = tid - DC_;
        float acc = bp_out[o];
        for (int p = 0; p < DP_; p++) acc = fmaf(sWV[DC_ + p], wp_out[p*DP_ + o], acc);
        out[(size_t)(B_*N_*DC_) + (size_t)bq*DP_ + o] = acc;
    }
}

// ============================= launch =============================
extern "C" void kernel_launch(void* const* d_in, const int* in_sizes, int n_in,
                              void* d_out, int out_size)
{
    const float* classes  = (const float*)d_in[0];
    const float* params   = (const float*)d_in[1];
    const float* edges    = (const float*)d_in[2];
    const float* wc_qkv   = (const float*)d_in[3];
    const float* bc_qkv   = (const float*)d_in[4];
    const float* wp_qkv   = (const float*)d_in[5];
    const float* bp_qkv   = (const float*)d_in[6];
    const float* fc_mul_w = (const float*)d_in[7];
    const float* fc_mul_b = (const float*)d_in[8];
    const float* fc_add_w = (const float*)d_in[9];
    const float* fc_add_b = (const float*)d_in[10];
    const float* fc_m1_w  = (const float*)d_in[11];
    const float* fc_m1_b  = (const float*)d_in[12];
    const float* fc_m2_w  = (const float*)d_in[13];
    const float* fc_m2_b  = (const float*)d_in[14];
    const float* fp_mul_w = (const float*)d_in[15];
    const float* fp_mul_b = (const float*)d_in[16];
    const float* fp_add_w = (const float*)d_in[17];
    const float* fp_add_b = (const float*)d_in[18];
    const float* fp_m1_w  = (const float*)d_in[19];
    const float* fp_m1_b  = (const float*)d_in[20];
    const float* fp_m2_w  = (const float*)d_in[21];
    const float* fp_m2_b  = (const float*)d_in[22];
    const float* wc_out   = (const float*)d_in[23];
    const float* bc_out   = (const float*)d_in[24];
    const float* wp_out   = (const float*)d_in[25];
    const float* bp_out   = (const float*)d_in[26];
    const float* we_out   = (const float*)d_in[27];
    const float* be_out   = (const float*)d_in[28];
    float* out = (float*)d_out;

    cudaFuncSetAttribute(fused_kernel,
                         cudaFuncAttributeMaxDynamicSharedMemorySize, SMEM_BYTES);

    const int pack_threads = 32768 + 18432 + 51200 + 16384;   // 118784
    pack_kernel<<<(pack_threads + NTHR - 1)/NTHR, NTHR>>>(
        fc_mul_w, fc_add_w, fc_m1_w, fc_m2_w,
        fp_mul_w, fp_add_w, fp_m1_w, fp_m2_w, we_out);
    prep_kernel<<<B_*N_, NTHR>>>(classes, params, wc_qkv, bc_qkv, wp_qkv, bp_qkv);
    fused_kernel<<<B_*N_, NTHR, SMEM_BYTES>>>(
        edges,
        fc_mul_b, fc_add_b, fc_m1_b, fc_m2_b,
        fp_mul_b, fp_add_b, fp_m1_b, fp_m2_b,
        wc_out, bc_out, wp_out, bp_out,
        be_out, out);
}

// round 17
// speedup vs baseline: 1.1867x; 1.1867x over previous
#include <cuda_runtime.h>
#include <cuda_bf16.h>
#include <cstdint>

#define NTHR 256
using ushort_t = unsigned short;

constexpr int B_  = 2;
constexpr int N_  = 256;
constexpr int DC_ = 96;
constexpr int DP_ = 160;
constexpr int DE_ = 64;
constexpr int H_  = 8;
constexpr int KT  = 64;        // k rows per tile
constexpr int NTC = 2;         // tiles per CTA (split-K: 2 CTAs per q)
constexpr int LDE = 72;        // bf16 elems
constexpr int LDX = 264;
constexpr int LDY = 200;
constexpr int LDWS = 40;       // staged weight row stride (ushorts): 16 hi + 16 lo + 8 pad
constexpr int WSB  = 20480;    // one weight buffer (bytes) = 256 rows * 80 B

// ---------------- device scratch (fp32) ----------------
__device__ float g_Qcat[B_*N_*256];   // [Qc*inv_sqrt96 | Qp*inv_sqrt160]
__device__ float g_Kcat[B_*N_*256];   // [Kc | Kp]
__device__ float g_Vc[B_*N_*DC_];
__device__ float g_Vp[B_*N_*DP_];
__device__ float g_ScC[B_*N_*N_*H_ / N_ * N_];  // [bq][k][h] raw class score sums
__device__ float g_ScP[B_*N_*N_*H_ / N_ * N_];  // (size 512*256*8 each)

// ---------------- split-bf16 weights, contiguous K16 chunks ----------------
// addr: (k>>4)*(N*32) + n*32 + (k&15)  (hi), +16 (lo). Chunk = N*32 ush contiguous.
__device__ __align__(16) ushort_t gW1mul[4*256*32];   // K=64,  N=256 (cat)
__device__ __align__(16) ushort_t gW1add[4*256*32];
__device__ __align__(16) ushort_t gWc1[6*96*32];      // K=96,  N=96
__device__ __align__(16) ushort_t gWc2[6*96*32];
__device__ __align__(16) ushort_t gWp1[10*160*32];    // K=160, N=160
__device__ __align__(16) ushort_t gWp2[10*160*32];
__device__ __align__(16) ushort_t gWe[16*64*32];      // K=256 (permuted), N=64

// ---------------- shared memory byte offsets ----------------
constexpr int OFFB_Q   = 0;        // 256 f
constexpr int OFFB_MB  = 1024;     // 256 f
constexpr int OFFB_AB  = 2048;     // 256 f
constexpr int OFFB_CB1 = 3072;     // 96 f
constexpr int OFFB_CB2 = 3456;
constexpr int OFFB_PB1 = 3840;     // 160 f
constexpr int OFFB_PB2 = 4480;
constexpr int OFFB_BE  = 5120;     // 64 f
constexpr int OFFB_EHI = 5376;     // 64*72 bf16 = 9216 B
constexpr int OFFB_ELO = 14592;
constexpr int OFFB_XHI = 23808;    // 64*264 bf16 = 33792 B
constexpr int OFFB_XLO = 57600;
constexpr int OFFB_YHI = 91392;    // 64*200 bf16 = 25600 B
constexpr int OFFB_YLO = 116992;
constexpr int OFFB_WS  = 142592;   // 2 * 20480 B ping-pong weight buffers
constexpr int SMEM_BYTES = 183552;

// ---------------- helpers ----------------
__device__ __forceinline__ float bf2f(ushort_t u) {
    return __uint_as_float(((unsigned)u) << 16);
}
__device__ __forceinline__ void split2(float x0, float x1, unsigned& hi, unsigned& lo) {
    const ushort_t h0 = __bfloat16_as_ushort(__float2bfloat16_rn(x0));
    const ushort_t h1 = __bfloat16_as_ushort(__float2bfloat16_rn(x1));
    const ushort_t l0 = __bfloat16_as_ushort(__float2bfloat16_rn(x0 - bf2f(h0)));
    const ushort_t l1 = __bfloat16_as_ushort(__float2bfloat16_rn(x1 - bf2f(h1)));
    hi = (unsigned)h0 | ((unsigned)h1 << 16);
    lo = (unsigned)l0 | ((unsigned)l1 << 16);
}
__device__ __forceinline__ void mma_bf16(float (&d)[4], const unsigned (&a)[4],
                                         const unsigned (&b)[2]) {
    asm("mma.sync.aligned.m16n8k16.row.col.f32.bf16.bf16.f32 "
        "{%0,%1,%2,%3},{%4,%5,%6,%7},{%8,%9},{%0,%1,%2,%3};"
        : "+f"(d[0]), "+f"(d[1]), "+f"(d[2]), "+f"(d[3])
        : "r"(a[0]), "r"(a[1]), "r"(a[2]), "r"(a[3]), "r"(b[0]), "r"(b[1]));
}
__device__ __forceinline__ float lrelu(float v) { return v > 0.f ? v : 0.05f * v; }

__device__ __forceinline__ uint32_t smem_u32(const void* p) {
    uint32_t a;
    asm("{ .reg .u64 t; cvta.to.shared.u64 t, %1; cvt.u32.u64 %0, t; }"
        : "=r"(a) : "l"(p));
    return a;
}
__device__ __forceinline__ void cpa16(uint32_t dst, const void* src) {
    asm volatile("cp.async.cg.shared.global [%0], [%1], 16;"
                 :: "r"(dst), "l"(src) : "memory");
}
#define CPA_COMMIT  asm volatile("cp.async.commit_group;" ::: "memory")
#define CPA_WAIT1   asm volatile("cp.async.wait_group 1;" ::: "memory")
#define CPA_WAIT0   asm volatile("cp.async.wait_group 0;" ::: "memory")

// global weight address (hi element; lo at +16)
__device__ __forceinline__ int waddr(int k, int n, int N) {
    return (k >> 4) * (N * 32) + n * 32 + (k & 15);
}

// ============================= prep: QKV =============================
__global__ void __launch_bounds__(NTHR) prep_kernel(
    const float* __restrict__ classes, const float* __restrict__ params,
    const float* __restrict__ wc_qkv,  const float* __restrict__ bc_qkv,
    const float* __restrict__ wp_qkv,  const float* __restrict__ bp_qkv)
{
    __shared__ float rc[DC_];
    __shared__ float rp[DP_];
    const int bn = blockIdx.x;
    const int t  = threadIdx.x;
    if (t < DC_) rc[t] = classes[bn*DC_ + t];
    if (t < DP_) rp[t] = params[bn*DP_ + t];
    __syncthreads();

    const float invc = 0.10206207261596575f;   // 1/sqrt(96)
    const float invp = 0.07905694150420949f;   // 1/sqrt(160)

    for (int o = t; o < 3*DC_; o += NTHR) {
        float acc = bc_qkv[o];
        #pragma unroll 4
        for (int i = 0; i < DC_; i++) acc = fmaf(rc[i], wc_qkv[i*3*DC_ + o], acc);
        const int part = o / DC_, d = o - part*DC_;
        if (part == 0)      g_Qcat[bn*256 + d] = acc * invc;
        else if (part == 1) g_Kcat[bn*256 + d] = acc;
        else                g_Vc[bn*DC_ + d] = acc;
    }
    for (int o = t; o < 3*DP_; o += NTHR) {
        float acc = bp_qkv[o];
        #pragma unroll 4
        for (int i = 0; i < DP_; i++) acc = fmaf(rp[i], wp_qkv[i*3*DP_ + o], acc);
        const int part = o / DP_, d = o - part*DP_;
        if (part == 0)      g_Qcat[bn*256 + 96 + d] = acc * invp;
        else if (part == 1) g_Kcat[bn*256 + 96 + d] = acc;
        else                g_Vp[bn*DP_ + d] = acc;
    }
}

// ============================= prep: weight split/pack =============================
__global__ void __launch_bounds__(NTHR) pack_kernel(
    const float* __restrict__ fc_mul_w, const float* __restrict__ fc_add_w,
    const float* __restrict__ fc_m1_w,  const float* __restrict__ fc_m2_w,
    const float* __restrict__ fp_mul_w, const float* __restrict__ fp_add_w,
    const float* __restrict__ fp_m1_w,  const float* __restrict__ fp_m2_w,
    const float* __restrict__ we_out)
{
    int i = blockIdx.x * NTHR + threadIdx.x;
    float v; ushort_t* dst; int addr;
    if (i < 32768) {                                   // W1 mul/add, K=64 N=256
        const bool isAdd = i >= 16384;
        const int t = i & 16383, k = t >> 8, n = t & 255;
        if (n < 96) v = (isAdd ? fc_add_w : fc_mul_w)[k*96 + n];
        else        v = (isAdd ? fp_add_w : fp_mul_w)[k*160 + n - 96];
        dst = isAdd ? gW1add : gW1mul; addr = waddr(k, n, 256);
    } else if ((i -= 32768) < 18432) {                 // Wc m1/m2, K=96 N=96
        const bool l2 = i >= 9216;
        const int t = l2 ? i - 9216 : i, k = t / 96, n = t % 96;
        v = (l2 ? fc_m2_w : fc_m1_w)[k*96 + n];
        dst = l2 ? gWc2 : gWc1; addr = waddr(k, n, 96);
    } else if ((i -= 18432) < 51200) {                 // Wp m1/m2, K=160 N=160
        const bool l2 = i >= 25600;
        const int t = l2 ? i - 25600 : i, k = t / 160, n = t % 160;
        v = (l2 ? fp_m2_w : fp_m1_w)[k*160 + n];
        dst = l2 ? gWp2 : gWp1; addr = waddr(k, n, 160);
    } else if ((i -= 51200) < 16384) {                 // We, K=256 (permuted) N=64
        const int k = i >> 6, n = i & 63;
        const int src = k < 96 ? (k/12)*32 + (k%12)
                               : ((k-96)/20)*32 + 12 + ((k-96)%20);
        v = we_out[src*64 + n];
        dst = gWe; addr = waddr(k, n, 64);
    } else return;
    const ushort_t h = __bfloat16_as_ushort(__float2bfloat16_rn(v));
    const ushort_t l = __bfloat16_as_ushort(__float2bfloat16_rn(v - bf2f(h)));
    dst[addr]      = h;
    dst[addr + 16] = l;
}

// ---------------- A fragment load (row-major bf16) ----------------
__device__ __forceinline__ void ldA(unsigned (&A)[4], const ushort_t* base,
                                    int lda, int row, int col) {
    const ushort_t* p = base + row*lda + col;
    A[0] = *reinterpret_cast<const unsigned*>(p);
    A[1] = *reinterpret_cast<const unsigned*>(p + 8*lda);
    A[2] = *reinterpret_cast<const unsigned*>(p + 8);
    A[3] = *reinterpret_cast<const unsigned*>(p + 8*lda + 8);
}

// ---------------- one K=16 chunk, 3-product split mma ----------------
template<int NTILES>
__device__ __forceinline__ void mma_chunk16(
    const ushort_t* __restrict__ Ahi, const ushort_t* __restrict__ Alo,
    int lda, int acol,
    const ushort_t* __restrict__ W, int nb,
    float (&acc)[2][NTILES][4], int lane, int mg)
{
    const int g = lane >> 2, t = lane & 3;
    unsigned Ah[2][4], Al[2][4];
    #pragma unroll
    for (int mt = 0; mt < 2; mt++) {
        const int row = mg*32 + mt*16 + g;
        const int col = acol + 2*t;
        ldA(Ah[mt], Ahi, lda, row, col);
        ldA(Al[mt], Alo, lda, row, col);
    }
    #pragma unroll
    for (int nt = 0; nt < NTILES; nt++) {
        const ushort_t* wp = W + (nb + nt*8 + g)*LDWS + 2*t;
        unsigned Bh[2], Bl[2];
        Bh[0] = *reinterpret_cast<const unsigned*>(wp);
        Bh[1] = *reinterpret_cast<const unsigned*>(wp + 8);
        Bl[0] = *reinterpret_cast<const unsigned*>(wp + 16);
        Bl[1] = *reinterpret_cast<const unsigned*>(wp + 24);
        #pragma unroll
        for (int mt = 0; mt < 2; mt++) {
            mma_bf16(acc[mt][nt], Ah[mt], Bh);
            mma_bf16(acc[mt][nt], Ah[mt], Bl);
            mma_bf16(acc[mt][nt], Al[mt], Bh);
        }
    }
}

// ---------------- cp.async chunk prefetch (K16 chunk = Nrows * 64 B) --------
__device__ __forceinline__ void prefetch_chunk(const ushort_t* __restrict__ gW,
                                               int ch, int Nrows,
                                               uint32_t dstaddr, int tid)
{
    const ushort_t* src = gW + ch * Nrows * 32;
    for (int u = tid; u < Nrows * 4; u += NTHR) {
        const int n = u >> 2, q = u & 3;
        cpa16(dstaddr + n*80 + q*16, src + n*32 + q*8);
    }
    CPA_COMMIT;
}

// ---------------- double-buffered pipelined GEMM driver ----------------
template<int NTILES, int NCH>
__device__ __forceinline__ void gemm_run(
    const ushort_t* __restrict__ gW, int Nrows,
    const ushort_t* __restrict__ Ahi, const ushort_t* __restrict__ Alo,
    int lda, int abase,
    ushort_t* sWS, uint32_t wsaddr, int nb, float (&acc)[2][NTILES][4],
    int tid, int lane, int mg)
{
    prefetch_chunk(gW, 0, Nrows, wsaddr, tid);
    #pragma unroll 1
    for (int ch = 0; ch < NCH; ch++) {
        if (ch + 1 < NCH) {
            prefetch_chunk(gW, ch + 1, Nrows, wsaddr + ((ch + 1) & 1) * WSB, tid);
            CPA_WAIT1;
        } else {
            CPA_WAIT0;
        }
        __syncthreads();
        mma_chunk16<NTILES>(Ahi, Alo, lda, abase + ch*16,
                            sWS + (ch & 1) * (WSB/2), nb, acc, lane, mg);
        __syncthreads();
    }
}

// ---------------- MLP epilogue: lrelu(acc + bias) -> split store ----------------
template<int NTILES>
__device__ __forceinline__ void mlp_epi(
    float (&acc)[2][NTILES][4], const float* __restrict__ bias, int nbase,
    ushort_t* __restrict__ Dhi, ushort_t* __restrict__ Dlo, int ldd, int coff,
    int lane, int mg)
{
    const int g = lane >> 2, t = lane & 3;
    #pragma unroll
    for (int mt = 0; mt < 2; mt++) {
        const int rb = mg*32 + mt*16 + g;
        #pragma unroll
        for (int nt = 0; nt < NTILES; nt++) {
            const int c = nbase + nt*8 + 2*t;
            const float b0 = bias[c], b1 = bias[c+1];
            unsigned h, l;
            split2(lrelu(acc[mt][nt][0] + b0), lrelu(acc[mt][nt][1] + b1), h, l);
            *reinterpret_cast<unsigned*>(&Dhi[rb*ldd + coff + c]) = h;
            *reinterpret_cast<unsigned*>(&Dlo[rb*ldd + coff + c]) = l;
            split2(lrelu(acc[mt][nt][2] + b0), lrelu(acc[mt][nt][3] + b1), h, l);
            *reinterpret_cast<unsigned*>(&Dhi[(rb+8)*ldd + coff + c]) = h;
            *reinterpret_cast<unsigned*>(&Dlo[(rb+8)*ldd + coff + c]) = l;
        }
    }
}

// ============================= fused main kernel (split-K) ====================
// grid = 1024: bq = blockIdx.x >> 1, k-half = blockIdx.x & 1 (2 tiles each).
__global__ void __launch_bounds__(NTHR, 1) fused_kernel(
    const float* __restrict__ edges,
    const float* __restrict__ fc_mul_b, const float* __restrict__ fc_add_b,
    const float* __restrict__ fc_m1_b,  const float* __restrict__ fc_m2_b,
    const float* __restrict__ fp_mul_b, const float* __restrict__ fp_add_b,
    const float* __restrict__ fp_m1_b,  const float* __restrict__ fp_m2_b,
    const float* __restrict__ be_out,
    float* __restrict__ out)
{
    extern __shared__ char smc[];
    float* sQ   = reinterpret_cast<float*>(smc + OFFB_Q);
    float* sMB  = reinterpret_cast<float*>(smc + OFFB_MB);
    float* sAB  = reinterpret_cast<float*>(smc + OFFB_AB);
    float* sCB1 = reinterpret_cast<float*>(smc + OFFB_CB1);
    float* sCB2 = reinterpret_cast<float*>(smc + OFFB_CB2);
    float* sPB1 = reinterpret_cast<float*>(smc + OFFB_PB1);
    float* sPB2 = reinterpret_cast<float*>(smc + OFFB_PB2);
    float* sBE  = reinterpret_cast<float*>(smc + OFFB_BE);
    ushort_t* sEhi = reinterpret_cast<ushort_t*>(smc + OFFB_EHI);
    ushort_t* sElo = reinterpret_cast<ushort_t*>(smc + OFFB_ELO);
    ushort_t* sXhi = reinterpret_cast<ushort_t*>(smc + OFFB_XHI);
    ushort_t* sXlo = reinterpret_cast<ushort_t*>(smc + OFFB_XLO);
    ushort_t* sYhi = reinterpret_cast<ushort_t*>(smc + OFFB_YHI);
    ushort_t* sYlo = reinterpret_cast<ushort_t*>(smc + OFFB_YLO);
    ushort_t* sWS  = reinterpret_cast<ushort_t*>(smc + OFFB_WS);
    const uint32_t wsaddr = smem_u32(smc + OFFB_WS);

    const int tid  = threadIdx.x;
    const int warp = tid >> 5;
    const int lane = tid & 31;
    const int mg   = warp >> 2;      // 0..1 row group (32 rows)
    const int ng   = warp & 3;       // 0..3 col group
    const int g    = lane >> 2, t4 = lane & 3;
    const int bq   = blockIdx.x >> 1;
    const int half = blockIdx.x & 1;
    const int b    = bq >> 8;

    // persistent stages
    for (int i = tid; i < 256; i += NTHR) sQ[i] = g_Qcat[bq*256 + i];
    for (int i = tid; i < DC_; i += NTHR) {
        sMB[i]  = fc_mul_b[i];  sAB[i]  = fc_add_b[i];
        sCB1[i] = fc_m1_b[i];   sCB2[i] = fc_m2_b[i];
    }
    for (int i = tid; i < DP_; i += NTHR) {
        sMB[96+i] = fp_mul_b[i];  sAB[96+i] = fp_add_b[i];
        sPB1[i]   = fp_m1_b[i];   sPB2[i]   = fp_m2_b[i];
    }
    if (tid < DE_) sBE[tid] = be_out[tid];

    const float* Eb = edges + (size_t)bq * N_ * DE_;
    float* outE = out + (size_t)(B_*N_*DC_ + B_*N_*DP_) + (size_t)bq * N_ * DE_;

    for (int tt = 0; tt < NTC; tt++) {
        const int k0 = half * 128 + tt * KT;
        __syncthreads();
        // ---- load + split E tile ----
        for (int idx = tid; idx < KT*32; idx += NTHR) {
            const int r = idx >> 5, kp = (idx & 31) * 2;
            const float2 e2 = *reinterpret_cast<const float2*>(
                &Eb[(size_t)(k0 + r)*DE_ + kp]);
            unsigned h, l; split2(e2.x, e2.y, h, l);
            *reinterpret_cast<unsigned*>(&sEhi[r*LDE + kp]) = h;
            *reinterpret_cast<unsigned*>(&sElo[r*LDE + kp]) = l;
        }
        // ========== stage 1 pass A: m = E @ Wmul + mb  -> split-store to X ====
        {
            float acc[2][8][4] = {};
            gemm_run<8,4>(gW1mul, 256, sEhi, sElo, LDE, 0, sWS, wsaddr, ng*64,
                          acc, tid, lane, mg);
            #pragma unroll
            for (int mt = 0; mt < 2; mt++) {
                const int rb = mg*32 + mt*16 + g;
                #pragma unroll
                for (int nt = 0; nt < 8; nt++) {
                    const int c = ng*64 + nt*8 + 2*t4;
                    const float mb0 = sMB[c], mb1 = sMB[c+1];
                    #pragma unroll
                    for (int hh = 0; hh < 2; hh++) {
                        const int r = rb + hh*8;
                        unsigned h, l;
                        split2(acc[mt][nt][2*hh+0] + mb0,
                               acc[mt][nt][2*hh+1] + mb1, h, l);
                        *reinterpret_cast<unsigned*>(&sXhi[r*LDX + c]) = h;
                        *reinterpret_cast<unsigned*>(&sXlo[r*LDX + c]) = l;
                    }
                }
            }
        }
        // ========== stage 1 pass B: add-GEMM + FiLM epilogue (reads m from X) ==
        {
            float acc[2][8][4] = {};
            gemm_run<8,4>(gW1add, 256, sEhi, sElo, LDE, 0, sWS, wsaddr, ng*64,
                          acc, tid, lane, mg);
            #pragma unroll
            for (int mt = 0; mt < 2; mt++) {
                const int rb = mg*32 + mt*16 + g;
                #pragma unroll
                for (int nt = 0; nt < 8; nt++) {
                    const int c = ng*64 + nt*8 + 2*t4;
                    const float q0 = sQ[c], q1 = sQ[c+1];
                    const float ab0 = sAB[c], ab1 = sAB[c+1];
                    #pragma unroll
                    for (int hh = 0; hh < 2; hh++) {
                        const int r = rb + hh*8;
                        const float m0 = bf2f(sXhi[r*LDX + c])
                                       + bf2f(sXlo[r*LDX + c]);
                        const float m1 = bf2f(sXhi[r*LDX + c + 1])
                                       + bf2f(sXlo[r*LDX + c + 1]);
                        const float2 kv = *reinterpret_cast<const float2*>(
                            &g_Kcat[(size_t)(b*N_ + k0 + r)*256 + c]);
                        const float a0 = q0 * kv.x, a1 = q1 * kv.y;
                        const float x0 = fmaf(a0, m0, acc[mt][nt][2*hh+0] + ab0 + a0);
                        const float x1 = fmaf(a1, m1, acc[mt][nt][2*hh+1] + ab1 + a1);
                        unsigned h, l; split2(x0, x1, h, l);
                        *reinterpret_cast<unsigned*>(&sXhi[r*LDX + c]) = h;
                        *reinterpret_cast<unsigned*>(&sXlo[r*LDX + c]) = l;
                    }
                }
            }
        }
        // ================= class MLP layer 1 (X[0:96] -> Y[0:96]) ============
        {
            float acc[2][3][4] = {};
            gemm_run<3,6>(gWc1, 96, sXhi, sXlo, LDX, 0, sWS, wsaddr, ng*24,
                          acc, tid, lane, mg);
            mlp_epi<3>(acc, sCB1, ng*24, sYhi, sYlo, LDY, 0, lane, mg);
        }
        // ================= class MLP layer 2 (Y[0:96] -> X[0:96]) ============
        {
            float acc[2][3][4] = {};
            gemm_run<3,6>(gWc2, 96, sYhi, sYlo, LDY, 0, sWS, wsaddr, ng*24,
                          acc, tid, lane, mg);
            mlp_epi<3>(acc, sCB2, ng*24, sXhi, sXlo, LDX, 0, lane, mg);
        }
        // ================= param MLP layer 1 (X[96:256] -> Y[0:160]) =========
        {
            float acc[2][5][4] = {};
            gemm_run<5,10>(gWp1, 160, sXhi, sXlo, LDX, 96, sWS, wsaddr, ng*40,
                           acc, tid, lane, mg);
            mlp_epi<5>(acc, sPB1, ng*40, sYhi, sYlo, LDY, 0, lane, mg);
        }
        // ================= param MLP layer 2 (Y[0:160] -> X[96:256]) =========
        {
            float acc[2][5][4] = {};
            gemm_run<5,10>(gWp2, 160, sYhi, sYlo, LDY, 0, sWS, wsaddr, ng*40,
                           acc, tid, lane, mg);
            mlp_epi<5>(acc, sPB2, ng*40, sXhi, sXlo, LDX, 96, lane, mg);
        }
        __syncthreads();
        // ---- per-head score sums from y2 -> GLOBAL score buffers ----
        for (int tau = tid; tau < KT*16; tau += NTHR) {
            const int r = tau >> 4;
            const int rest = tau & 15;
            const int h = rest >> 1;
            float s = 0.f;
            if ((rest & 1) == 0) {
                const int base = r*LDX + h*12;
                #pragma unroll
                for (int d = 0; d < 12; d++)
                    s += bf2f(sXhi[base+d]) + bf2f(sXlo[base+d]);
                g_ScC[(size_t)bq*2048 + (k0 + r)*H_ + h] = s;
            } else {
                const int base = r*LDX + 96 + h*20;
                #pragma unroll
                for (int d = 0; d < 20; d++)
                    s += bf2f(sXhi[base+d]) + bf2f(sXlo[base+d]);
                g_ScP[(size_t)bq*2048 + (k0 + r)*H_ + h] = s;
            }
        }
        // ================= out_e GEMM (X[0:256] -> 64) =======================
        {
            float acc[2][2][4] = {};
            gemm_run<2,16>(gWe, 64, sXhi, sXlo, LDX, 0, sWS, wsaddr, ng*16,
                           acc, tid, lane, mg);
            #pragma unroll
            for (int mt = 0; mt < 2; mt++) {
                const int rb = mg*32 + mt*16 + g;
                #pragma unroll
                for (int nt = 0; nt < 2; nt++) {
                    const int c = ng*16 + nt*8 + 2*t4;
                    const float b0 = sBE[c], b1 = sBE[c+1];
                    float2 v0, v1;
                    v0.x = acc[mt][nt][0] + b0; v0.y = acc[mt][nt][1] + b1;
                    v1.x = acc[mt][nt][2] + b0; v1.y = acc[mt][nt][3] + b1;
                    *reinterpret_cast<float2*>(&outE[(size_t)(k0 + rb)*DE_ + c]) = v0;
                    *reinterpret_cast<float2*>(&outE[(size_t)(k0 + rb + 8)*DE_ + c]) = v1;
                }
            }
        }
    }
}

// ============================= finish kernel ==================================
// softmax over k per head, weighted V (cross), output projections.
__global__ void __launch_bounds__(NTHR) finish_kernel(
    const float* __restrict__ wc_out, const float* __restrict__ bc_out,
    const float* __restrict__ wp_out, const float* __restrict__ bp_out,
    float* __restrict__ out)
{
    __shared__ float sScC[N_*H_];
    __shared__ float sScP[N_*H_];
    __shared__ float sWV[256];
    const int tid  = threadIdx.x;
    const int warp = tid >> 5;
    const int lane = tid & 31;
    const int bq   = blockIdx.x;
    const int b    = bq >> 8;

    for (int i = tid; i < N_*H_; i += NTHR) {
        sScC[i] = g_ScC[(size_t)bq*2048 + i];
        sScP[i] = g_ScP[(size_t)bq*2048 + i];
    }
    __syncthreads();

    // softmax per head (warp h owns head h; class then param)
    {
        const int h = warp;
        #pragma unroll
        for (int ty = 0; ty < 2; ty++) {
            float* S = ty ? sScP : sScC;
            float m = -1e30f;
            for (int k = lane; k < N_; k += 32) m = fmaxf(m, S[k*H_ + h]);
            #pragma unroll
            for (int o = 16; o; o >>= 1) m = fmaxf(m, __shfl_xor_sync(0xffffffffu, m, o));
            float sum = 0.f;
            for (int k = lane; k < N_; k += 32) {
                const float e = __expf(S[k*H_ + h] - m);
                S[k*H_ + h] = e;
                sum += e;
            }
            #pragma unroll
            for (int o = 16; o; o >>= 1) sum += __shfl_xor_sync(0xffffffffu, sum, o);
            const float inv = 1.f / sum;
            for (int k = lane; k < N_; k += 32) S[k*H_ + h] *= inv;
        }
    }
    __syncthreads();

    // weighted V (cross: ap weights Vc, ac weights Vp)
    {
        float acc = 0.f;
        if (tid < DC_) {
            const int c = tid, h = c / 12;
            const float* V = g_Vc + (size_t)(b*N_) * DC_ + c;
            for (int k = 0; k < N_; k++) acc = fmaf(sScP[k*H_ + h], V[(size_t)k*DC_], acc);
        } else {
            const int p = tid - DC_, h = p / 20;
            const float* V = g_Vp + (size_t)(b*N_) * DP_ + p;
            for (int k = 0; k < N_; k++) acc = fmaf(sScC[k*H_ + h], V[(size_t)k*DP_], acc);
        }
        sWV[tid] = acc;
    }
    __syncthreads();

    // output projections
    if (tid < DC_) {
        const int o = tid;
        float acc = bc_out[o];
        for (int c = 0; c < DC_; c++) acc = fmaf(sWV[c], wc_out[c*DC_ + o], acc);
        out[(size_t)bq*DC_ + o] = acc;
    } else {
        const int o = tid - DC_;
        float acc = bp_out[o];
        for (int p = 0; p < DP_; p++) acc = fmaf(sWV[DC_ + p], wp_out[p*DP_ + o], acc);
        out[(size_t)(B_*N_*DC_) + (size_t)bq*DP_ + o] = acc;
    }
}

// ============================= launch =============================
extern "C" void kernel_launch(void* const* d_in, const int* in_sizes, int n_in,
                              void* d_out, int out_size)
{
    const float* classes  = (const float*)d_in[0];
    const float* params   = (const float*)d_in[1];
    const float* edges    = (const float*)d_in[2];
    const float* wc_qkv   = (const float*)d_in[3];
    const float* bc_qkv   = (const float*)d_in[4];
    const float* wp_qkv   = (const float*)d_in[5];
    const float* bp_qkv   = (const float*)d_in[6];
    const float* fc_mul_w = (const float*)d_in[7];
    const float* fc_mul_b = (const float*)d_in[8];
    const float* fc_add_w = (const float*)d_in[9];
    const float* fc_add_b = (const float*)d_in[10];
    const float* fc_m1_w  = (const float*)d_in[11];
    const float* fc_m1_b  = (const float*)d_in[12];
    const float* fc_m2_w  = (const float*)d_in[13];
    const float* fc_m2_b  = (const float*)d_in[14];
    const float* fp_mul_w = (const float*)d_in[15];
    const float* fp_mul_b = (const float*)d_in[16];
    const float* fp_add_w = (const float*)d_in[17];
    const float* fp_add_b = (const float*)d_in[18];
    const float* fp_m1_w  = (const float*)d_in[19];
    const float* fp_m1_b  = (const float*)d_in[20];
    const float* fp_m2_w  = (const float*)d_in[21];
    const float* fp_m2_b  = (const float*)d_in[22];
    const float* wc_out   = (const float*)d_in[23];
    const float* bc_out   = (const float*)d_in[24];
    const float* wp_out   = (const float*)d_in[25];
    const float* bp_out   = (const float*)d_in[26];
    const float* we_out   = (const float*)d_in[27];
    const float* be_out   = (const float*)d_in[28];
    float* out = (float*)d_out;

    cudaFuncSetAttribute(fused_kernel,
                         cudaFuncAttributeMaxDynamicSharedMemorySize, SMEM_BYTES);

    const int pack_threads = 32768 + 18432 + 51200 + 16384;   // 118784
    pack_kernel<<<(pack_threads + NTHR - 1)/NTHR, NTHR>>>(
        fc_mul_w, fc_add_w, fc_m1_w, fc_m2_w,
        fp_mul_w, fp_add_w, fp_m1_w, fp_m2_w, we_out);
    prep_kernel<<<B_*N_, NTHR>>>(classes, params, wc_qkv, bc_qkv, wp_qkv, bp_qkv);
    fused_kernel<<<2*B_*N_, NTHR, SMEM_BYTES>>>(
        edges,
        fc_mul_b, fc_add_b, fc_m1_b, fc_m2_b,
        fp_mul_b, fp_add_b, fp_m1_b, fp_m2_b,
        be_out, out);
    finish_kernel<<<B_*N_, NTHR>>>(wc_out, bc_out, wp_out, bp_out, out);
}